// round 7
// baseline (speedup 1.0000x reference)
#include <cuda_runtime.h>
#include <cuda_bf16.h>
#include <math.h>
#include <float.h>
#include <stdint.h>

// ---------------- problem constants ----------------
#define T_TOK 8192
#define HD    2048
#define ID    1024
#define KQ    8
#define NE    128
#define KI    8192
#define I2    2048

// ---------------- fp32 scratch ----------------
__device__ float g_gate[67108864];   // [T, KI]
__device__ float g_up[67108864];     // [T, KI]
__device__ float g_sg[16777216];     // [T, I2]
__device__ float g_su[16777216];     // [T, I2]
__device__ float g_zf[8388608];      // [T, ID]
__device__ float g_hf[16777216];     // [T, I2]
__device__ float g_logits[1048576];  // [T, NE]
__device__ float g_wk[65536];        // [T, KQ]
__device__ float g_mix[1024];        // [NE, KQ]

// ---------------- int8 limb scratch ----------------
__device__ int8_t q_x1[16777216],  q_x2[16777216];    // x [T,HD]
__device__ int8_t q_wg1[16777216], q_wg2[16777216];   // w_gate^T [KI,HD]
__device__ int8_t q_wu1[16777216], q_wu2[16777216];   // w_up^T
__device__ int8_t q_wd1[2097152],  q_wd2[2097152];    // w_down^T [HD,ID]
__device__ int8_t q_sg1[4194304],  q_sg2[4194304];    // shared_w_gate^T [I2,HD]
__device__ int8_t q_su1[4194304],  q_su2[4194304];    // shared_w_up^T
__device__ int8_t q_sd1[4194304],  q_sd2[4194304];    // shared_w_down^T [HD,I2]
__device__ int8_t q_z1[8388608],   q_z2[8388608];     // z [T,ID]
__device__ int8_t q_h1[16777216],  q_h2[16777216];    // h [T,I2]

// bf16 (router only)
__device__ __nv_bfloat16 g_xh[16777216], g_xl[16777216];
__device__ __nv_bfloat16 g_wrh[262144],  g_wrl[262144];

// scales: 0=x 1=weights 2=z 3=h
__device__ float    g_sv[4];
__device__ float    g_iv[4];
__device__ unsigned g_um[2];

// ================= low-level helpers =================
__device__ __forceinline__ uint32_t smem_u32(const void* p) {
    uint32_t a;
    asm("{ .reg .u64 t; cvta.to.shared.u64 t, %1; cvt.u32.u64 %0, t; }" : "=r"(a) : "l"(p));
    return a;
}
__device__ __forceinline__ void cp16(uint32_t dst, const void* src) {
    asm volatile("cp.async.cg.shared.global [%0], [%1], 16;" :: "r"(dst), "l"(src));
}
__device__ __forceinline__ void cp_commit() {
    asm volatile("cp.async.commit_group;" ::: "memory");
}
template<int N> __device__ __forceinline__ void cp_wait() {
    asm volatile("cp.async.wait_group %0;" :: "n"(N) : "memory");
}
__device__ __forceinline__ void ldsm4(uint32_t* r, uint32_t addr) {
    asm volatile("ldmatrix.sync.aligned.m8n8.x4.shared.b16 {%0,%1,%2,%3}, [%4];"
                 : "=r"(r[0]), "=r"(r[1]), "=r"(r[2]), "=r"(r[3]) : "r"(addr));
}
__device__ __forceinline__ void ldsm4t(uint32_t* r, uint32_t addr) {
    asm volatile("ldmatrix.sync.aligned.m8n8.x4.trans.shared.b16 {%0,%1,%2,%3}, [%4];"
                 : "=r"(r[0]), "=r"(r[1]), "=r"(r[2]), "=r"(r[3]) : "r"(addr));
}
__device__ __forceinline__ void mma16816(float* d, const uint32_t* a, uint32_t b0, uint32_t b1) {
    asm volatile("mma.sync.aligned.m16n8k16.row.col.f32.bf16.bf16.f32 "
                 "{%0,%1,%2,%3}, {%4,%5,%6,%7}, {%8,%9}, {%0,%1,%2,%3};"
                 : "+f"(d[0]), "+f"(d[1]), "+f"(d[2]), "+f"(d[3])
                 : "r"(a[0]), "r"(a[1]), "r"(a[2]), "r"(a[3]), "r"(b0), "r"(b1));
}
__device__ __forceinline__ void imma16832(int* d, const uint32_t* a, uint32_t b0, uint32_t b1) {
    asm volatile("mma.sync.aligned.m16n8k32.row.col.s32.s8.s8.s32 "
                 "{%0,%1,%2,%3}, {%4,%5,%6,%7}, {%8,%9}, {%0,%1,%2,%3};"
                 : "+r"(d[0]), "+r"(d[1]), "+r"(d[2]), "+r"(d[3])
                 : "r"(a[0]), "r"(a[1]), "r"(a[2]), "r"(a[3]), "r"(b0), "r"(b1));
}

// ================= int8 2-limb GEMM =================
// C[M,N] = sA*sB*(a1+a2/256)(b1+b2/256)-ish : passes a1b1 (acc1), a1b2+a2b1 (accc)
// A limbs: [M,Kd] row-major int8. B limbs: [N,Kd] row-major int8 (pre-transposed).
// Block 128x64, BK=64, 256 threads (8 warps: 4 m-strips x 2 n-strips, warp 32x32), 2 CTAs/SM.
#define QBM 128
#define QBN 64
#define QA_STR 80                  // 64 + 16 pad
#define QSA (QBM * QA_STR)         // 10240 per limb
#define QSB (QBN * QA_STR)         // 5120 per limb
#define QSTAGE (2 * QSA + 2 * QSB) // 30720
#define QSMEM (2 * QSTAGE)         // 61440

__global__ __launch_bounds__(256, 2)
void qgemm_kernel(const int8_t* __restrict__ A1, const int8_t* __restrict__ A2,
                  const int8_t* __restrict__ B1, const int8_t* __restrict__ B2,
                  float* __restrict__ C, int N, int Kd,
                  const float* __restrict__ psa, const float* __restrict__ psb, int acc)
{
    extern __shared__ char smem[];
    const uint32_t sb = smem_u32(smem);
    const int tid = threadIdx.x, lane = tid & 31, wid = tid >> 5;
    const int wr = wid & 3, wc = wid >> 2;
    const int row0 = blockIdx.x * QBM, col0 = blockIdx.y * QBN;
    const int nch = Kd >> 6;

    int acc1[2][4][4], accc[2][4][4];
#pragma unroll
    for (int i = 0; i < 2; i++)
#pragma unroll
        for (int j = 0; j < 4; j++)
#pragma unroll
            for (int q = 0; q < 4; q++) { acc1[i][j][q] = 0; accc[i][j][q] = 0; }

    auto load_stage = [&](int stg, int k0) {
        uint32_t s0 = sb + stg * QSTAGE;
#pragma unroll
        for (int it = 0; it < 4; it++) {          // A: 128 rows x 4 chunks x 2 limbs
            int idx = it * 256 + tid;
            int r = idx >> 3, rem = idx & 7;
            int limb = rem >> 2, c = rem & 3;
            const int8_t* g = (limb ? A2 : A1) + (size_t)(row0 + r) * Kd + k0 + c * 16;
            cp16(s0 + limb * QSA + r * QA_STR + c * 16, g);
        }
#pragma unroll
        for (int it = 0; it < 2; it++) {          // B: 64 rows x 4 chunks x 2 limbs
            int idx = it * 256 + tid;
            int r = idx >> 3, rem = idx & 7;
            int limb = rem >> 2, c = rem & 3;
            const int8_t* g = (limb ? B2 : B1) + (size_t)(col0 + r) * Kd + k0 + c * 16;
            cp16(s0 + 2 * QSA + limb * QSB + r * QA_STR + c * 16, g);
        }
        cp_commit();
    };

    load_stage(0, 0);

    // A fragment mapping (m16n8k32 expects a0:r0-7/k0-15, a1:r8-15/k0-15,
    // a2:r0-7/k16-31, a3:r8-15/k16-31): lanes 0-15 -> rows 0-15 at k-chunk 0,
    // lanes 16-31 -> rows 0-15 at +16B.  (R6 bug: a1/a2 were swapped.)
    const uint32_t a_lrow = lane & 15;
    const uint32_t a_lk   = (uint32_t)(lane >> 4) << 4;
    const uint32_t a_off  = (uint32_t)(wr * 32 + a_lrow) * QA_STR + a_lk;
    // B fragment mapping: mat order {n0-7:k0, n0-7:k16, n8-15:k0, n8-15:k16}.
    const uint32_t b_lrow = (lane & 7) + ((lane >> 4) << 3);
    const uint32_t b_lk   = (uint32_t)((lane >> 3) & 1) << 4;
    const uint32_t b_off  = (uint32_t)(wc * 32 + b_lrow) * QA_STR + b_lk;

    for (int ch = 0; ch < nch; ch++) {
        cp_wait<0>();
        __syncthreads();
        if (ch + 1 < nch) load_stage((ch + 1) & 1, (ch + 1) << 6);

        uint32_t sA = sb + (ch & 1) * QSTAGE;
        uint32_t sB = sA + 2 * QSA;

#pragma unroll
        for (int ks = 0; ks < 2; ks++) {
            const uint32_t kofs = ks * 32;
            uint32_t af[2][2][4];   // [mi][limb]
#pragma unroll
            for (int mi = 0; mi < 2; mi++)
#pragma unroll
                for (int lb = 0; lb < 2; lb++)
                    ldsm4(af[mi][lb], sA + lb * QSA + a_off + mi * 16 * QA_STR + kofs);
            uint32_t bf[2][2][4];   // [pair][limb]; pair p: regs{0,1}=nj 2p, {2,3}=nj 2p+1
#pragma unroll
            for (int p = 0; p < 2; p++)
#pragma unroll
                for (int lb = 0; lb < 2; lb++)
                    ldsm4(bf[p][lb], sB + lb * QSB + b_off + p * 16 * QA_STR + kofs);
#pragma unroll
            for (int mi = 0; mi < 2; mi++)
#pragma unroll
                for (int nj = 0; nj < 4; nj++) {
                    int p = nj >> 1, o = (nj & 1) << 1;
                    imma16832(acc1[mi][nj], af[mi][0], bf[p][0][o], bf[p][0][o + 1]);
                    imma16832(accc[mi][nj], af[mi][0], bf[p][1][o], bf[p][1][o + 1]);
                    imma16832(accc[mi][nj], af[mi][1], bf[p][0][o], bf[p][0][o + 1]);
                }
        }
    }

    const float sAB = (*psa) * (*psb);
    const int er = row0 + wr * 32 + (lane >> 2);
    const int ec = col0 + wc * 32 + (lane & 3) * 2;
#pragma unroll
    for (int mi = 0; mi < 2; mi++)
#pragma unroll
        for (int nj = 0; nj < 4; nj++) {
            float v0 = sAB * ((float)acc1[mi][nj][0] + (float)accc[mi][nj][0] * (1.f / 256.f));
            float v1 = sAB * ((float)acc1[mi][nj][1] + (float)accc[mi][nj][1] * (1.f / 256.f));
            float v2 = sAB * ((float)acc1[mi][nj][2] + (float)accc[mi][nj][2] * (1.f / 256.f));
            float v3 = sAB * ((float)acc1[mi][nj][3] + (float)accc[mi][nj][3] * (1.f / 256.f));
            float* p0 = C + (size_t)(er + mi * 16) * N + ec + nj * 8;
            float* p1 = p0 + 8 * N;
            if (acc) {
                float2 o0 = *(float2*)p0, o1 = *(float2*)p1;
                v0 += o0.x; v1 += o0.y; v2 += o1.x; v3 += o1.y;
            }
            *(float2*)p0 = make_float2(v0, v1);
            *(float2*)p1 = make_float2(v2, v3);
        }
}

// ================= quantization =================
__device__ __forceinline__ void quant2(float v, float inv, int8_t& o1, int8_t& o2)
{
    float q = v * inv;
    float a1 = rintf(fminf(fmaxf(q, -126.f), 126.f));
    float a2 = rintf(fminf(fmaxf((q - a1) * 256.f, -127.f), 127.f));
    o1 = (int8_t)a1; o2 = (int8_t)a2;
}

__global__ void quantA_kernel(const float4* __restrict__ src, const float* __restrict__ pinv,
                              int8_t* __restrict__ a1, int8_t* __restrict__ a2, int n4)
{
    int i = blockIdx.x * 256 + threadIdx.x;
    if (i >= n4) return;
    float4 v = src[i];
    float inv = *pinv;
    int8_t p1[4], p2[4];
    quant2(v.x, inv, p1[0], p2[0]);
    quant2(v.y, inv, p1[1], p2[1]);
    quant2(v.z, inv, p1[2], p2[2]);
    quant2(v.w, inv, p1[3], p2[3]);
    *(uint32_t*)(a1 + i * 4) = *(uint32_t*)p1;
    *(uint32_t*)(a2 + i * 4) = *(uint32_t*)p2;
}

// transpose + quantize: W [Kd, Nd] fp32 -> b1,b2 [Nd, Kd] int8
__global__ void quantBT_kernel(const float* __restrict__ W, int Kd, int Nd,
                               const float* __restrict__ pinv,
                               int8_t* __restrict__ b1, int8_t* __restrict__ b2)
{
    __shared__ float tile[32][33];
    int k0 = blockIdx.x * 32;
    int n0 = blockIdx.y * 32;
    int tx = threadIdx.x & 31;
    int ty = threadIdx.x >> 5;
#pragma unroll
    for (int i = 0; i < 4; i++)
        tile[ty + 8 * i][tx] = W[(size_t)(k0 + ty + 8 * i) * Nd + n0 + tx];
    __syncthreads();
    float inv = *pinv;
    int n = threadIdx.x >> 3;
    int kq = (threadIdx.x & 7) * 4;
    int8_t p1[4], p2[4];
#pragma unroll
    for (int j = 0; j < 4; j++)
        quant2(tile[kq + j][n], inv, p1[j], p2[j]);
    size_t o = (size_t)(n0 + n) * Kd + k0 + kq;
    *(uint32_t*)(b1 + o) = *(uint32_t*)p1;
    *(uint32_t*)(b2 + o) = *(uint32_t*)p2;
}

__global__ void init_consts()
{
    g_sv[0] = 6.0f / 126.f;  g_iv[0] = 126.f / 6.0f;
    g_sv[1] = 0.13f / 126.f; g_iv[1] = 126.f / 0.13f;
    g_um[0] = 0u; g_um[1] = 0u;
}

__global__ void finalize_scale(int i)
{
    float m = fmaxf(__uint_as_float(g_um[i - 2]), 1e-6f);
    g_sv[i] = m / 126.f;
    g_iv[i] = 126.f / m;
}

// block-level abs-max reduce + one atomic
__device__ __forceinline__ void block_absmax(float am, unsigned* dst)
{
    __shared__ float rm[8];
#pragma unroll
    for (int o = 16; o; o >>= 1) am = fmaxf(am, __shfl_xor_sync(0xffffffffu, am, o));
    int w = threadIdx.x >> 5;
    if ((threadIdx.x & 31) == 0) rm[w] = am;
    __syncthreads();
    if (threadIdx.x == 0) {
        float m = rm[0];
#pragma unroll
        for (int i = 1; i < 8; i++) m = fmaxf(m, rm[i]);
        atomicMax(dst, __float_as_uint(m));
    }
}

// ================= bf16 hi/lo GEMM (router only) =================
#define BM 128
#define BK 64
#define A_STR 144
#define SA_HALF (BM * A_STR)

template<int BN_T>
__global__ __launch_bounds__(512, 1)
void hmma3_kernel(const __nv_bfloat16* __restrict__ Ah, const __nv_bfloat16* __restrict__ Al,
                  const __nv_bfloat16* __restrict__ Bh, const __nv_bfloat16* __restrict__ Bl,
                  float* __restrict__ C, int N, int Kd, int acc)
{
    constexpr int WN      = BN_T / 4;
    constexpr int NH      = BN_T / 64;
    constexpr int B_STR_T = BN_T * 2 + 16;
    constexpr int SB_HALF = BK * B_STR_T;
    constexpr int STAGEB  = 2 * SA_HALF + 2 * SB_HALF;
    constexpr int NBCH    = BN_T / 8;
    constexpr int B_ITERS = (BK * NBCH) / 512;

    extern __shared__ char smem[];
    const uint32_t sb = smem_u32(smem);
    const int tid  = threadIdx.x;
    const int lane = tid & 31;
    const int wid  = tid >> 5;
    const int wr   = wid & 3;
    const int wc   = wid >> 2;
    const int row0 = blockIdx.x * BM;
    const int col0 = blockIdx.y * BN_T;
    const int nch  = Kd >> 6;

    float accf[2][2 * NH][4];
#pragma unroll
    for (int i = 0; i < 2; i++)
#pragma unroll
        for (int j = 0; j < 2 * NH; j++)
#pragma unroll
            for (int q = 0; q < 4; q++) accf[i][j][q] = 0.f;

    auto load_stage = [&](int stg, int k0) {
        uint32_t s0 = sb + stg * STAGEB;
#pragma unroll
        for (int it = 0; it < 2; it++) {
            int idx = it * 512 + tid;
            int r = idx >> 3, c = idx & 7;
            const __nv_bfloat16* gh = Ah + (size_t)(row0 + r) * Kd + k0 + c * 8;
            const __nv_bfloat16* gl = Al + (size_t)(row0 + r) * Kd + k0 + c * 8;
            uint32_t d = s0 + r * A_STR + c * 16;
            cp16(d, gh);
            cp16(d + SA_HALF, gl);
        }
#pragma unroll
        for (int it = 0; it < B_ITERS; it++) {
            int idx = it * 512 + tid;
            int r = idx / NBCH, c = idx % NBCH;
            const __nv_bfloat16* gh = Bh + (size_t)(k0 + r) * N + col0 + c * 8;
            const __nv_bfloat16* gl = Bl + (size_t)(k0 + r) * N + col0 + c * 8;
            uint32_t d = s0 + 2 * SA_HALF + r * B_STR_T + c * 16;
            cp16(d, gh);
            cp16(d + SB_HALF, gl);
        }
        cp_commit();
    };

    load_stage(0, 0);

    const int a_row  = wr * 32 + (lane & 15);
    const int a_colb = (lane >> 4) << 4;
    const int b_row  = lane & 15;
    const int b_colb = (wc * WN + ((lane >> 4) << 3)) * 2;

    for (int ch = 0; ch < nch; ch++) {
        cp_wait<0>();
        __syncthreads();
        if (ch + 1 < nch) load_stage((ch + 1) & 1, (ch + 1) << 6);

        uint32_t sA = sb + (ch & 1) * STAGEB;
        uint32_t sB = sA + 2 * SA_HALF;

#pragma unroll
        for (int ks = 0; ks < 4; ks++) {
            const int k16 = ks << 4;
            uint32_t Ahf[2][4], Alf[2][4];
#pragma unroll
            for (int mi = 0; mi < 2; mi++) {
                uint32_t ad = sA + (a_row + mi * 16) * A_STR + k16 * 2 + a_colb;
                ldsm4(Ahf[mi], ad);
                ldsm4(Alf[mi], ad + SA_HALF);
            }
#pragma unroll
            for (int nh = 0; nh < NH; nh++) {
                uint32_t Bhf[4], Blf[4];
                uint32_t bd = sB + (b_row + k16) * B_STR_T + b_colb + nh * 32;
                ldsm4t(Bhf, bd);
                ldsm4t(Blf, bd + SB_HALF);
#pragma unroll
                for (int mi = 0; mi < 2; mi++)
#pragma unroll
                    for (int q = 0; q < 2; q++) {
                        float* d = accf[mi][nh * 2 + q];
                        mma16816(d, Ahf[mi], Bhf[q * 2], Bhf[q * 2 + 1]);
                        mma16816(d, Alf[mi], Bhf[q * 2], Bhf[q * 2 + 1]);
                        mma16816(d, Ahf[mi], Blf[q * 2], Blf[q * 2 + 1]);
                    }
            }
        }
    }

    const int er = row0 + wr * 32 + (lane >> 2);
    const int ec = col0 + wc * WN + (lane & 3) * 2;
#pragma unroll
    for (int mi = 0; mi < 2; mi++)
#pragma unroll
        for (int ni = 0; ni < 2 * NH; ni++) {
            float* p0 = C + (size_t)(er + mi * 16) * N + ec + ni * 8;
            float* p1 = p0 + 8 * N;
            float v0 = accf[mi][ni][0], v1 = accf[mi][ni][1];
            float v2 = accf[mi][ni][2], v3 = accf[mi][ni][3];
            if (acc) {
                float2 o0 = *(float2*)p0, o1 = *(float2*)p1;
                v0 += o0.x; v1 += o0.y; v2 += o1.x; v3 += o1.y;
            }
            *(float2*)p0 = make_float2(v0, v1);
            *(float2*)p1 = make_float2(v2, v3);
        }
}
#define SMEM_128 (2 * (2 * SA_HALF + 2 * (BK * (128 * 2 + 16))))

// ================= split fp32 -> bf16 hi/lo (router operands) =================
__global__ void split_kernel(const float4* __restrict__ src,
                             __nv_bfloat16* __restrict__ hi,
                             __nv_bfloat16* __restrict__ lo, int n4)
{
    int i = blockIdx.x * 256 + threadIdx.x;
    if (i >= n4) return;
    float4 v = src[i];
    __nv_bfloat16 h0 = __float2bfloat16_rn(v.x), h1 = __float2bfloat16_rn(v.y);
    __nv_bfloat16 h2 = __float2bfloat16_rn(v.z), h3 = __float2bfloat16_rn(v.w);
    __nv_bfloat162 hh0 = {h0, h1}, hh1 = {h2, h3};
    __nv_bfloat162 ll0 = {__float2bfloat16_rn(v.x - __bfloat162float(h0)),
                          __float2bfloat16_rn(v.y - __bfloat162float(h1))};
    __nv_bfloat162 ll1 = {__float2bfloat16_rn(v.z - __bfloat162float(h2)),
                          __float2bfloat16_rn(v.w - __bfloat162float(h3))};
    *(__nv_bfloat162*)(hi + i * 4)     = hh0;
    *(__nv_bfloat162*)(hi + i * 4 + 2) = hh1;
    *(__nv_bfloat162*)(lo + i * 4)     = ll0;
    *(__nv_bfloat162*)(lo + i * 4 + 2) = ll1;
}

// ================= amplitudes -> normalized mix =================
__global__ void mix_kernel(const float* __restrict__ amp)
{
    int e = threadIdx.x;
    if (e >= NE) return;
    float p[KQ];
    float s = 0.f;
#pragma unroll
    for (int k = 0; k < KQ; k++) {
        float a0 = amp[(e * KQ + k) * 2 + 0];
        float a1 = amp[(e * KQ + k) * 2 + 1];
        p[k] = a0 * a0 + a1 * a1;
        s += p[k];
    }
    float inv = 1.f / (s + 1e-8f);
#pragma unroll
    for (int k = 0; k < KQ; k++) g_mix[e * KQ + k] = p[k] * inv;
}

// ================= softmax + top-4 + collapse =================
__global__ void topk_kernel(const float* __restrict__ expert_scale)
{
    int lane = threadIdx.x & 31;
    int warp = threadIdx.x >> 5;
    int t = blockIdx.x * 8 + warp;
    const float* lrow = g_logits + (size_t)t * NE;

    float v[4];
#pragma unroll
    for (int j = 0; j < 4; j++) v[j] = lrow[lane + 32 * j];

    float m = fmaxf(fmaxf(v[0], v[1]), fmaxf(v[2], v[3]));
#pragma unroll
    for (int o = 16; o; o >>= 1) m = fmaxf(m, __shfl_xor_sync(0xffffffffu, m, o));

    float D = 0.f;
#pragma unroll
    for (int j = 0; j < 4; j++) D += expf(v[j] - m);
#pragma unroll
    for (int o = 16; o; o >>= 1) D += __shfl_xor_sync(0xffffffffu, D, o);

    float lv[4] = {v[0], v[1], v[2], v[3]};
    float selv[4];
    int   seli[4];
#pragma unroll
    for (int it = 0; it < 4; it++) {
        float bv = -FLT_MAX;
        int   bi = NE;
#pragma unroll
        for (int j = 0; j < 4; j++) {
            int e = lane + 32 * j;
            if (lv[j] > bv) { bv = lv[j]; bi = e; }
        }
#pragma unroll
        for (int o = 16; o; o >>= 1) {
            float ov = __shfl_xor_sync(0xffffffffu, bv, o);
            int   oi = __shfl_xor_sync(0xffffffffu, bi, o);
            if (ov > bv || (ov == bv && oi < bi)) { bv = ov; bi = oi; }
        }
        selv[it] = bv;
        seli[it] = bi;
        if ((bi & 31) == lane) lv[bi >> 5] = -FLT_MAX;
    }

    float ew[4];
    float S = 0.f;
#pragma unroll
    for (int it = 0; it < 4; it++) { ew[it] = expf(selv[it] - m); S += ew[it]; }
    float denom = S + 1e-8f * D;

    if (lane < KQ) {
        float acc = 0.f;
#pragma unroll
        for (int it = 0; it < 4; it++)
            acc += (ew[it] / denom) * expert_scale[seli[it]] * g_mix[seli[it] * KQ + lane];
        g_wk[t * KQ + lane] = acc;
    }
}

// ================= z = sum_k wk * silu(gate) * up (fp32 + absmax) =================
__global__ void moe_mix_kernel()
{
    int t = blockIdx.y;
    int i = blockIdx.x * 256 + threadIdx.x;
    __shared__ float w[KQ];
    if (threadIdx.x < KQ) w[threadIdx.x] = g_wk[t * KQ + threadIdx.x];
    __syncthreads();
    float acc = 0.f;
#pragma unroll
    for (int k = 0; k < KQ; k++) {
        size_t off = (size_t)t * KI + k * ID + i;
        float g = g_gate[off];
        float u = g_up[off];
        acc += w[k] * (g / (1.f + expf(-g))) * u;
    }
    g_zf[(size_t)t * ID + i] = acc;
    block_absmax(fabsf(acc), &g_um[0]);
}

// ================= shared expert elementwise (fp32 + absmax) =================
__global__ void silu_mul_kernel()
{
    size_t idx = (size_t)blockIdx.x * 256 + threadIdx.x;
    float g = g_sg[idx];
    float u = g_su[idx];
    float v = (g / (1.f + expf(-g))) * u;
    g_hf[idx] = v;
    block_absmax(fabsf(v), &g_um[1]);
}

// ================= host side =================
static void qgemm(const void* A1, const void* A2, const void* B1, const void* B2,
                  float* C, int M, int N, int Kd, const float* psa, const float* psb, int acc)
{
    dim3 grid(M / QBM, N / QBN);
    qgemm_kernel<<<grid, 256, QSMEM>>>(
        (const int8_t*)A1, (const int8_t*)A2, (const int8_t*)B1, (const int8_t*)B2,
        C, N, Kd, psa, psb, acc);
}

extern "C" void kernel_launch(void* const* d_in, const int* in_sizes, int n_in,
                              void* d_out, int out_size)
{
    const float* x             = (const float*)d_in[0];
    const float* w_router      = (const float*)d_in[1];
    const float* w_gate        = (const float*)d_in[2];
    const float* w_up          = (const float*)d_in[3];
    const float* w_down        = (const float*)d_in[4];
    const float* amplitudes    = (const float*)d_in[5];
    const float* expert_scale  = (const float*)d_in[6];
    const float* shared_w_gate = (const float*)d_in[7];
    const float* shared_w_up   = (const float*)d_in[8];
    const float* shared_w_down = (const float*)d_in[9];
    float* out = (float*)d_out;

    cudaFuncSetAttribute(qgemm_kernel, cudaFuncAttributeMaxDynamicSharedMemorySize, QSMEM);
    cudaFuncSetAttribute(hmma3_kernel<128>, cudaFuncAttributeMaxDynamicSharedMemorySize, SMEM_128);

    void *px1, *px2, *pwg1, *pwg2, *pwu1, *pwu2, *pwd1, *pwd2;
    void *psg1, *psg2, *psu1, *psu2, *psd1, *psd2;
    void *pz1, *pz2, *ph1, *ph2;
    void *pg, *pu, *psg, *psu, *pzf, *phf, *plog;
    void *pxh, *pxl, *pwrh, *pwrl, *psv, *piv;
    cudaGetSymbolAddress(&px1, q_x1);   cudaGetSymbolAddress(&px2, q_x2);
    cudaGetSymbolAddress(&pwg1, q_wg1); cudaGetSymbolAddress(&pwg2, q_wg2);
    cudaGetSymbolAddress(&pwu1, q_wu1); cudaGetSymbolAddress(&pwu2, q_wu2);
    cudaGetSymbolAddress(&pwd1, q_wd1); cudaGetSymbolAddress(&pwd2, q_wd2);
    cudaGetSymbolAddress(&psg1, q_sg1); cudaGetSymbolAddress(&psg2, q_sg2);
    cudaGetSymbolAddress(&psu1, q_su1); cudaGetSymbolAddress(&psu2, q_su2);
    cudaGetSymbolAddress(&psd1, q_sd1); cudaGetSymbolAddress(&psd2, q_sd2);
    cudaGetSymbolAddress(&pz1, q_z1);   cudaGetSymbolAddress(&pz2, q_z2);
    cudaGetSymbolAddress(&ph1, q_h1);   cudaGetSymbolAddress(&ph2, q_h2);
    cudaGetSymbolAddress(&pg, g_gate);  cudaGetSymbolAddress(&pu, g_up);
    cudaGetSymbolAddress(&psg, g_sg);   cudaGetSymbolAddress(&psu, g_su);
    cudaGetSymbolAddress(&pzf, g_zf);   cudaGetSymbolAddress(&phf, g_hf);
    cudaGetSymbolAddress(&plog, g_logits);
    cudaGetSymbolAddress(&pxh, g_xh);   cudaGetSymbolAddress(&pxl, g_xl);
    cudaGetSymbolAddress(&pwrh, g_wrh); cudaGetSymbolAddress(&pwrl, g_wrl);
    cudaGetSymbolAddress(&psv, g_sv);   cudaGetSymbolAddress(&piv, g_iv);
    float* sv = (float*)psv;
    float* iv = (float*)piv;

    // 0. constants + scale init
    init_consts<<<1, 1>>>();

    // 1. quantize activations (fixed x scale) and weights (fixed scale, transposed)
    quantA_kernel<<<(T_TOK * HD / 4) / 256, 256>>>((const float4*)x, iv + 0, (int8_t*)px1, (int8_t*)px2, T_TOK * HD / 4);
    quantBT_kernel<<<dim3(HD / 32, KI / 32), 256>>>(w_gate, HD, KI, iv + 1, (int8_t*)pwg1, (int8_t*)pwg2);
    quantBT_kernel<<<dim3(HD / 32, KI / 32), 256>>>(w_up,   HD, KI, iv + 1, (int8_t*)pwu1, (int8_t*)pwu2);
    quantBT_kernel<<<dim3(ID / 32, HD / 32), 256>>>(w_down, ID, HD, iv + 1, (int8_t*)pwd1, (int8_t*)pwd2);
    quantBT_kernel<<<dim3(HD / 32, I2 / 32), 256>>>(shared_w_gate, HD, I2, iv + 1, (int8_t*)psg1, (int8_t*)psg2);
    quantBT_kernel<<<dim3(HD / 32, I2 / 32), 256>>>(shared_w_up,   HD, I2, iv + 1, (int8_t*)psu1, (int8_t*)psu2);
    quantBT_kernel<<<dim3(I2 / 32, HD / 32), 256>>>(shared_w_down, I2, HD, iv + 1, (int8_t*)psd1, (int8_t*)psd2);

    // 2. router path in bf16x3 (precision-sensitive)
    split_kernel<<<(T_TOK * HD / 4) / 256, 256>>>((const float4*)x, (__nv_bfloat16*)pxh, (__nv_bfloat16*)pxl, T_TOK * HD / 4);
    split_kernel<<<(HD * NE / 4) / 256, 256>>>((const float4*)w_router, (__nv_bfloat16*)pwrh, (__nv_bfloat16*)pwrl, HD * NE / 4);
    mix_kernel<<<1, 128>>>(amplitudes);
    hmma3_kernel<128><<<dim3(T_TOK / BM, 1), 512, SMEM_128>>>(
        (const __nv_bfloat16*)pxh, (const __nv_bfloat16*)pxl,
        (const __nv_bfloat16*)pwrh, (const __nv_bfloat16*)pwrl, (float*)plog, NE, HD, 0);
    topk_kernel<<<T_TOK / 8, 256>>>(expert_scale);

    // 3. gate / up projections (int8)
    qgemm(px1, px2, pwg1, pwg2, (float*)pg, T_TOK, KI, HD, sv + 0, sv + 1, 0);
    qgemm(px1, px2, pwu1, pwu2, (float*)pu, T_TOK, KI, HD, sv + 0, sv + 1, 0);

    // 4. z = sum_k wk * silu(gate) * up; dynamic scale; quantize
    moe_mix_kernel<<<dim3(ID / 256, T_TOK), 256>>>();
    finalize_scale<<<1, 1>>>(2);
    quantA_kernel<<<(T_TOK * ID / 4) / 256, 256>>>((const float4*)pzf, iv + 2, (int8_t*)pz1, (int8_t*)pz2, T_TOK * ID / 4);

    // 5. down projection
    qgemm(pz1, pz2, pwd1, pwd2, out, T_TOK, HD, ID, sv + 2, sv + 1, 0);

    // 6. shared expert
    qgemm(px1, px2, psg1, psg2, (float*)psg, T_TOK, I2, HD, sv + 0, sv + 1, 0);
    qgemm(px1, px2, psu1, psu2, (float*)psu, T_TOK, I2, HD, sv + 0, sv + 1, 0);
    silu_mul_kernel<<<(T_TOK * I2) / 256, 256>>>();
    finalize_scale<<<1, 1>>>(3);
    quantA_kernel<<<(T_TOK * I2 / 4) / 256, 256>>>((const float4*)phf, iv + 3, (int8_t*)ph1, (int8_t*)ph2, T_TOK * I2 / 4);

    // 7. out += h @ shared_w_down
    qgemm(ph1, ph2, psd1, psd2, out, T_TOK, HD, I2, sv + 3, sv + 1, 1);
}

// round 8
// speedup vs baseline: 3.7905x; 3.7905x over previous
#include <cuda_runtime.h>
#include <cuda_bf16.h>
#include <cuda_fp16.h>
#include <math.h>
#include <float.h>
#include <stdint.h>

// ---------------- problem constants ----------------
#define T_TOK 8192
#define HD    2048
#define ID    1024
#define KQ    8
#define NE    128
#define KI    8192
#define I2    2048

// ---------------- fp32 scratch ----------------
__device__ float g_gate[67108864];   // [T, KI]
__device__ float g_up[67108864];     // [T, KI]
__device__ float g_sg[16777216];     // [T, I2]
__device__ float g_su[16777216];     // [T, I2]
__device__ float g_logits[1048576];  // [T, NE]
__device__ float g_wk[65536];        // [T, KQ]
__device__ float g_mix[1024];        // [NE, KQ]

// ---------------- fp16 operand scratch ----------------
__device__ __half h_xh[16777216], h_xl[16777216];   // x limbs [T,HD]
__device__ __half h_wg[16777216];                   // w_gate [HD,KI] single limb
__device__ __half h_wu[16777216];                   // w_up
__device__ __half h_wd[2097152];                    // w_down [ID,HD]
__device__ __half h_sg[4194304];                    // shared_w_gate [HD,I2]
__device__ __half h_su[4194304];                    // shared_w_up
__device__ __half h_sd[4194304];                    // shared_w_down [I2,HD]
__device__ __half h_zh[8388608],  h_zl[8388608];    // z limbs [T,ID]
__device__ __half h_hh[16777216], h_hl[16777216];   // h limbs [T,I2]

// bf16 (router only)
__device__ __nv_bfloat16 g_xh[16777216], g_xl[16777216];
__device__ __nv_bfloat16 g_wrh[262144],  g_wrl[262144];

// ================= low-level helpers =================
__device__ __forceinline__ uint32_t smem_u32(const void* p) {
    uint32_t a;
    asm("{ .reg .u64 t; cvta.to.shared.u64 t, %1; cvt.u32.u64 %0, t; }" : "=r"(a) : "l"(p));
    return a;
}
__device__ __forceinline__ void cp16(uint32_t dst, const void* src) {
    asm volatile("cp.async.cg.shared.global [%0], [%1], 16;" :: "r"(dst), "l"(src));
}
__device__ __forceinline__ void cp_commit() {
    asm volatile("cp.async.commit_group;" ::: "memory");
}
template<int N> __device__ __forceinline__ void cp_wait() {
    asm volatile("cp.async.wait_group %0;" :: "n"(N) : "memory");
}
__device__ __forceinline__ void ldsm4(uint32_t* r, uint32_t addr) {
    asm volatile("ldmatrix.sync.aligned.m8n8.x4.shared.b16 {%0,%1,%2,%3}, [%4];"
                 : "=r"(r[0]), "=r"(r[1]), "=r"(r[2]), "=r"(r[3]) : "r"(addr));
}
__device__ __forceinline__ void ldsm4t(uint32_t* r, uint32_t addr) {
    asm volatile("ldmatrix.sync.aligned.m8n8.x4.trans.shared.b16 {%0,%1,%2,%3}, [%4];"
                 : "=r"(r[0]), "=r"(r[1]), "=r"(r[2]), "=r"(r[3]) : "r"(addr));
}
__device__ __forceinline__ void mma_bf16(float* d, const uint32_t* a, uint32_t b0, uint32_t b1) {
    asm volatile("mma.sync.aligned.m16n8k16.row.col.f32.bf16.bf16.f32 "
                 "{%0,%1,%2,%3}, {%4,%5,%6,%7}, {%8,%9}, {%0,%1,%2,%3};"
                 : "+f"(d[0]), "+f"(d[1]), "+f"(d[2]), "+f"(d[3])
                 : "r"(a[0]), "r"(a[1]), "r"(a[2]), "r"(a[3]), "r"(b0), "r"(b1));
}
__device__ __forceinline__ void mma_f16(float* d, const uint32_t* a, uint32_t b0, uint32_t b1) {
    asm volatile("mma.sync.aligned.m16n8k16.row.col.f32.f16.f16.f32 "
                 "{%0,%1,%2,%3}, {%4,%5,%6,%7}, {%8,%9}, {%0,%1,%2,%3};"
                 : "+f"(d[0]), "+f"(d[1]), "+f"(d[2]), "+f"(d[3])
                 : "r"(a[0]), "r"(a[1]), "r"(a[2]), "r"(a[3]), "r"(b0), "r"(b1));
}

#define BM 128
#define BK 64
#define A_STR 144
#define SA_HALF (BM * A_STR)

// ================= fp16 2-pass GEMM: C = (Ah+Al) @ B =================
// A limbs [M,Kd] fp16 row-major; B [Kd,N] fp16 row-major; C fp32.
// Block 128 x BN_T, BK=64, 512 threads (16 warps, warp 32 x BN_T/4), 2-stage.
template<int BN_T>
__global__ __launch_bounds__(512, 1)
void hmma2_kernel(const __half* __restrict__ Ah, const __half* __restrict__ Al,
                  const __half* __restrict__ B, float* __restrict__ C,
                  int N, int Kd, int acc)
{
    constexpr int WN      = BN_T / 4;
    constexpr int NH      = BN_T / 64;
    constexpr int B_STR_T = BN_T * 2 + 16;
    constexpr int SB      = BK * B_STR_T;
    constexpr int STAGEB  = 2 * SA_HALF + SB;
    constexpr int NBCH    = BN_T / 8;
    constexpr int B_ITERS = (BK * NBCH) / 512;

    extern __shared__ char smem[];
    const uint32_t sb = smem_u32(smem);
    const int tid  = threadIdx.x;
    const int lane = tid & 31;
    const int wid  = tid >> 5;
    const int wr   = wid & 3;
    const int wc   = wid >> 2;
    const int row0 = blockIdx.x * BM;
    const int col0 = blockIdx.y * BN_T;
    const int nch  = Kd >> 6;

    float accf[2][2 * NH][4];
#pragma unroll
    for (int i = 0; i < 2; i++)
#pragma unroll
        for (int j = 0; j < 2 * NH; j++)
#pragma unroll
            for (int q = 0; q < 4; q++) accf[i][j][q] = 0.f;

    auto load_stage = [&](int stg, int k0) {
        uint32_t s0 = sb + stg * STAGEB;
#pragma unroll
        for (int it = 0; it < 2; it++) {           // A: 128 rows x 8 chunks x 2 limbs
            int idx = it * 512 + tid;
            int r = idx >> 3, c = idx & 7;
            const __half* gh = Ah + (size_t)(row0 + r) * Kd + k0 + c * 8;
            const __half* gl = Al + (size_t)(row0 + r) * Kd + k0 + c * 8;
            uint32_t d = s0 + r * A_STR + c * 16;
            cp16(d, gh);
            cp16(d + SA_HALF, gl);
        }
#pragma unroll
        for (int it = 0; it < B_ITERS; it++) {     // B: 64 rows x NBCH chunks
            int idx = it * 512 + tid;
            int r = idx / NBCH, c = idx % NBCH;
            const __half* g = B + (size_t)(k0 + r) * N + col0 + c * 8;
            cp16(s0 + 2 * SA_HALF + r * B_STR_T + c * 16, g);
        }
        cp_commit();
    };

    load_stage(0, 0);

    const int a_row  = wr * 32 + (lane & 15);
    const int a_colb = (lane >> 4) << 4;
    const int b_row  = lane & 15;
    const int b_colb = (wc * WN + ((lane >> 4) << 3)) * 2;

    for (int ch = 0; ch < nch; ch++) {
        cp_wait<0>();
        __syncthreads();
        if (ch + 1 < nch) load_stage((ch + 1) & 1, (ch + 1) << 6);

        uint32_t sA = sb + (ch & 1) * STAGEB;
        uint32_t sB = sA + 2 * SA_HALF;

#pragma unroll
        for (int ks = 0; ks < 4; ks++) {
            const int k16 = ks << 4;
            uint32_t Ahf[2][4], Alf[2][4];
#pragma unroll
            for (int mi = 0; mi < 2; mi++) {
                uint32_t ad = sA + (a_row + mi * 16) * A_STR + k16 * 2 + a_colb;
                ldsm4(Ahf[mi], ad);
                ldsm4(Alf[mi], ad + SA_HALF);
            }
#pragma unroll
            for (int nh = 0; nh < NH; nh++) {
                uint32_t Bf[4];
                ldsm4t(Bf, sB + (b_row + k16) * B_STR_T + b_colb + nh * 32);
#pragma unroll
                for (int mi = 0; mi < 2; mi++)
#pragma unroll
                    for (int q = 0; q < 2; q++) {
                        float* d = accf[mi][nh * 2 + q];
                        mma_f16(d, Ahf[mi], Bf[q * 2], Bf[q * 2 + 1]);
                        mma_f16(d, Alf[mi], Bf[q * 2], Bf[q * 2 + 1]);
                    }
            }
        }
    }

    const int er = row0 + wr * 32 + (lane >> 2);
    const int ec = col0 + wc * WN + (lane & 3) * 2;
#pragma unroll
    for (int mi = 0; mi < 2; mi++)
#pragma unroll
        for (int ni = 0; ni < 2 * NH; ni++) {
            float* p0 = C + (size_t)(er + mi * 16) * N + ec + ni * 8;
            float* p1 = p0 + 8 * N;
            float v0 = accf[mi][ni][0], v1 = accf[mi][ni][1];
            float v2 = accf[mi][ni][2], v3 = accf[mi][ni][3];
            if (acc) {
                float2 o0 = *(float2*)p0, o1 = *(float2*)p1;
                v0 += o0.x; v1 += o0.y; v2 += o1.x; v3 += o1.y;
            }
            *(float2*)p0 = make_float2(v0, v1);
            *(float2*)p1 = make_float2(v2, v3);
        }
}
#define SMEM_H256 (2 * (2 * SA_HALF + BK * (256 * 2 + 16)))   // 141312

// ================= bf16 hi/lo 3-pass GEMM (router only) =================
template<int BN_T>
__global__ __launch_bounds__(512, 1)
void hmma3_kernel(const __nv_bfloat16* __restrict__ Ah, const __nv_bfloat16* __restrict__ Al,
                  const __nv_bfloat16* __restrict__ Bh, const __nv_bfloat16* __restrict__ Bl,
                  float* __restrict__ C, int N, int Kd, int acc)
{
    constexpr int WN      = BN_T / 4;
    constexpr int NH      = BN_T / 64;
    constexpr int B_STR_T = BN_T * 2 + 16;
    constexpr int SB_HALF = BK * B_STR_T;
    constexpr int STAGEB  = 2 * SA_HALF + 2 * SB_HALF;
    constexpr int NBCH    = BN_T / 8;
    constexpr int B_ITERS = (BK * NBCH) / 512;

    extern __shared__ char smem[];
    const uint32_t sb = smem_u32(smem);
    const int tid  = threadIdx.x;
    const int lane = tid & 31;
    const int wid  = tid >> 5;
    const int wr   = wid & 3;
    const int wc   = wid >> 2;
    const int row0 = blockIdx.x * BM;
    const int col0 = blockIdx.y * BN_T;
    const int nch  = Kd >> 6;

    float accf[2][2 * NH][4];
#pragma unroll
    for (int i = 0; i < 2; i++)
#pragma unroll
        for (int j = 0; j < 2 * NH; j++)
#pragma unroll
            for (int q = 0; q < 4; q++) accf[i][j][q] = 0.f;

    auto load_stage = [&](int stg, int k0) {
        uint32_t s0 = sb + stg * STAGEB;
#pragma unroll
        for (int it = 0; it < 2; it++) {
            int idx = it * 512 + tid;
            int r = idx >> 3, c = idx & 7;
            const __nv_bfloat16* gh = Ah + (size_t)(row0 + r) * Kd + k0 + c * 8;
            const __nv_bfloat16* gl = Al + (size_t)(row0 + r) * Kd + k0 + c * 8;
            uint32_t d = s0 + r * A_STR + c * 16;
            cp16(d, gh);
            cp16(d + SA_HALF, gl);
        }
#pragma unroll
        for (int it = 0; it < B_ITERS; it++) {
            int idx = it * 512 + tid;
            int r = idx / NBCH, c = idx % NBCH;
            const __nv_bfloat16* gh = Bh + (size_t)(k0 + r) * N + col0 + c * 8;
            const __nv_bfloat16* gl = Bl + (size_t)(k0 + r) * N + col0 + c * 8;
            uint32_t d = s0 + 2 * SA_HALF + r * B_STR_T + c * 16;
            cp16(d, gh);
            cp16(d + SB_HALF, gl);
        }
        cp_commit();
    };

    load_stage(0, 0);

    const int a_row  = wr * 32 + (lane & 15);
    const int a_colb = (lane >> 4) << 4;
    const int b_row  = lane & 15;
    const int b_colb = (wc * WN + ((lane >> 4) << 3)) * 2;

    for (int ch = 0; ch < nch; ch++) {
        cp_wait<0>();
        __syncthreads();
        if (ch + 1 < nch) load_stage((ch + 1) & 1, (ch + 1) << 6);

        uint32_t sA = sb + (ch & 1) * STAGEB;
        uint32_t sB = sA + 2 * SA_HALF;

#pragma unroll
        for (int ks = 0; ks < 4; ks++) {
            const int k16 = ks << 4;
            uint32_t Ahf[2][4], Alf[2][4];
#pragma unroll
            for (int mi = 0; mi < 2; mi++) {
                uint32_t ad = sA + (a_row + mi * 16) * A_STR + k16 * 2 + a_colb;
                ldsm4(Ahf[mi], ad);
                ldsm4(Alf[mi], ad + SA_HALF);
            }
#pragma unroll
            for (int nh = 0; nh < NH; nh++) {
                uint32_t Bhf[4], Blf[4];
                uint32_t bd = sB + (b_row + k16) * B_STR_T + b_colb + nh * 32;
                ldsm4t(Bhf, bd);
                ldsm4t(Blf, bd + SB_HALF);
#pragma unroll
                for (int mi = 0; mi < 2; mi++)
#pragma unroll
                    for (int q = 0; q < 2; q++) {
                        float* d = accf[mi][nh * 2 + q];
                        mma_bf16(d, Ahf[mi], Bhf[q * 2], Bhf[q * 2 + 1]);
                        mma_bf16(d, Alf[mi], Bhf[q * 2], Bhf[q * 2 + 1]);
                        mma_bf16(d, Ahf[mi], Blf[q * 2], Blf[q * 2 + 1]);
                    }
            }
        }
    }

    const int er = row0 + wr * 32 + (lane >> 2);
    const int ec = col0 + wc * WN + (lane & 3) * 2;
#pragma unroll
    for (int mi = 0; mi < 2; mi++)
#pragma unroll
        for (int ni = 0; ni < 2 * NH; ni++) {
            float* p0 = C + (size_t)(er + mi * 16) * N + ec + ni * 8;
            float* p1 = p0 + 8 * N;
            float v0 = accf[mi][ni][0], v1 = accf[mi][ni][1];
            float v2 = accf[mi][ni][2], v3 = accf[mi][ni][3];
            if (acc) {
                float2 o0 = *(float2*)p0, o1 = *(float2*)p1;
                v0 += o0.x; v1 += o0.y; v2 += o1.x; v3 += o1.y;
            }
            *(float2*)p0 = make_float2(v0, v1);
            *(float2*)p1 = make_float2(v2, v3);
        }
}
#define SMEM_128 (2 * (2 * SA_HALF + 2 * (BK * (128 * 2 + 16))))

// ================= conversions =================
// fp32 -> fp16 hi/lo limbs
__global__ void splitH_kernel(const float4* __restrict__ src,
                              __half* __restrict__ hi, __half* __restrict__ lo, int n4)
{
    int i = blockIdx.x * 256 + threadIdx.x;
    if (i >= n4) return;
    float4 v = src[i];
    __half h0 = __float2half_rn(v.x), h1 = __float2half_rn(v.y);
    __half h2 = __float2half_rn(v.z), h3 = __float2half_rn(v.w);
    __half l0 = __float2half_rn(v.x - __half2float(h0));
    __half l1 = __float2half_rn(v.y - __half2float(h1));
    __half l2 = __float2half_rn(v.z - __half2float(h2));
    __half l3 = __float2half_rn(v.w - __half2float(h3));
    __half2* hp = (__half2*)(hi + i * 4);
    __half2* lp = (__half2*)(lo + i * 4);
    hp[0] = __halves2half2(h0, h1); hp[1] = __halves2half2(h2, h3);
    lp[0] = __halves2half2(l0, l1); lp[1] = __halves2half2(l2, l3);
}

// fp32 -> single fp16
__global__ void conv1_kernel(const float4* __restrict__ src, __half* __restrict__ dst, int n4)
{
    int i = blockIdx.x * 256 + threadIdx.x;
    if (i >= n4) return;
    float4 v = src[i];
    __half2* dp = (__half2*)(dst + i * 4);
    dp[0] = __floats2half2_rn(v.x, v.y);
    dp[1] = __floats2half2_rn(v.z, v.w);
}

// fp32 -> bf16 hi/lo (router)
__global__ void split_kernel(const float4* __restrict__ src,
                             __nv_bfloat16* __restrict__ hi,
                             __nv_bfloat16* __restrict__ lo, int n4)
{
    int i = blockIdx.x * 256 + threadIdx.x;
    if (i >= n4) return;
    float4 v = src[i];
    __nv_bfloat16 h0 = __float2bfloat16_rn(v.x), h1 = __float2bfloat16_rn(v.y);
    __nv_bfloat16 h2 = __float2bfloat16_rn(v.z), h3 = __float2bfloat16_rn(v.w);
    __nv_bfloat162 hh0 = {h0, h1}, hh1 = {h2, h3};
    __nv_bfloat162 ll0 = {__float2bfloat16_rn(v.x - __bfloat162float(h0)),
                          __float2bfloat16_rn(v.y - __bfloat162float(h1))};
    __nv_bfloat162 ll1 = {__float2bfloat16_rn(v.z - __bfloat162float(h2)),
                          __float2bfloat16_rn(v.w - __bfloat162float(h3))};
    *(__nv_bfloat162*)(hi + i * 4)     = hh0;
    *(__nv_bfloat162*)(hi + i * 4 + 2) = hh1;
    *(__nv_bfloat162*)(lo + i * 4)     = ll0;
    *(__nv_bfloat162*)(lo + i * 4 + 2) = ll1;
}

// ================= amplitudes -> normalized mix =================
__global__ void mix_kernel(const float* __restrict__ amp)
{
    int e = threadIdx.x;
    if (e >= NE) return;
    float p[KQ];
    float s = 0.f;
#pragma unroll
    for (int k = 0; k < KQ; k++) {
        float a0 = amp[(e * KQ + k) * 2 + 0];
        float a1 = amp[(e * KQ + k) * 2 + 1];
        p[k] = a0 * a0 + a1 * a1;
        s += p[k];
    }
    float inv = 1.f / (s + 1e-8f);
#pragma unroll
    for (int k = 0; k < KQ; k++) g_mix[e * KQ + k] = p[k] * inv;
}

// ================= softmax + top-4 + collapse =================
__global__ void topk_kernel(const float* __restrict__ expert_scale)
{
    int lane = threadIdx.x & 31;
    int warp = threadIdx.x >> 5;
    int t = blockIdx.x * 8 + warp;
    const float* lrow = g_logits + (size_t)t * NE;

    float v[4];
#pragma unroll
    for (int j = 0; j < 4; j++) v[j] = lrow[lane + 32 * j];

    float m = fmaxf(fmaxf(v[0], v[1]), fmaxf(v[2], v[3]));
#pragma unroll
    for (int o = 16; o; o >>= 1) m = fmaxf(m, __shfl_xor_sync(0xffffffffu, m, o));

    float D = 0.f;
#pragma unroll
    for (int j = 0; j < 4; j++) D += expf(v[j] - m);
#pragma unroll
    for (int o = 16; o; o >>= 1) D += __shfl_xor_sync(0xffffffffu, D, o);

    float lv[4] = {v[0], v[1], v[2], v[3]};
    float selv[4];
    int   seli[4];
#pragma unroll
    for (int it = 0; it < 4; it++) {
        float bv = -FLT_MAX;
        int   bi = NE;
#pragma unroll
        for (int j = 0; j < 4; j++) {
            int e = lane + 32 * j;
            if (lv[j] > bv) { bv = lv[j]; bi = e; }
        }
#pragma unroll
        for (int o = 16; o; o >>= 1) {
            float ov = __shfl_xor_sync(0xffffffffu, bv, o);
            int   oi = __shfl_xor_sync(0xffffffffu, bi, o);
            if (ov > bv || (ov == bv && oi < bi)) { bv = ov; bi = oi; }
        }
        selv[it] = bv;
        seli[it] = bi;
        if ((bi & 31) == lane) lv[bi >> 5] = -FLT_MAX;
    }

    float ew[4];
    float S = 0.f;
#pragma unroll
    for (int it = 0; it < 4; it++) { ew[it] = expf(selv[it] - m); S += ew[it]; }
    float denom = S + 1e-8f * D;

    if (lane < KQ) {
        float acc = 0.f;
#pragma unroll
        for (int it = 0; it < 4; it++)
            acc += (ew[it] / denom) * expert_scale[seli[it]] * g_mix[seli[it] * KQ + lane];
        g_wk[t * KQ + lane] = acc;
    }
}

// ================= z = sum_k wk * silu(gate) * up  (writes fp16 limbs) =================
__global__ void moe_mix_kernel()
{
    int t = blockIdx.y;
    int i = blockIdx.x * 256 + threadIdx.x;
    __shared__ float w[KQ];
    if (threadIdx.x < KQ) w[threadIdx.x] = g_wk[t * KQ + threadIdx.x];
    __syncthreads();
    float acc = 0.f;
#pragma unroll
    for (int k = 0; k < KQ; k++) {
        size_t off = (size_t)t * KI + k * ID + i;
        float g = g_gate[off];
        float u = g_up[off];
        acc += w[k] * (g / (1.f + expf(-g))) * u;
    }
    size_t zo = (size_t)t * ID + i;
    __half h = __float2half_rn(acc);
    h_zh[zo] = h;
    h_zl[zo] = __float2half_rn(acc - __half2float(h));
}

// ================= shared expert elementwise (writes fp16 limbs) =================
__global__ void silu_mul_kernel()
{
    size_t idx = (size_t)blockIdx.x * 256 + threadIdx.x;
    float g = g_sg[idx];
    float u = g_su[idx];
    float v = (g / (1.f + expf(-g))) * u;
    __half h = __float2half_rn(v);
    h_hh[idx] = h;
    h_hl[idx] = __float2half_rn(v - __half2float(h));
}

// ================= host side =================
static void gemm2(const void* Ah, const void* Al, const void* B,
                  float* C, int M, int N, int Kd, int acc)
{
    dim3 grid(M / BM, N / 256);
    hmma2_kernel<256><<<grid, 512, SMEM_H256>>>(
        (const __half*)Ah, (const __half*)Al, (const __half*)B, C, N, Kd, acc);
}

extern "C" void kernel_launch(void* const* d_in, const int* in_sizes, int n_in,
                              void* d_out, int out_size)
{
    const float* x             = (const float*)d_in[0];
    const float* w_router      = (const float*)d_in[1];
    const float* w_gate        = (const float*)d_in[2];
    const float* w_up          = (const float*)d_in[3];
    const float* w_down        = (const float*)d_in[4];
    const float* amplitudes    = (const float*)d_in[5];
    const float* expert_scale  = (const float*)d_in[6];
    const float* shared_w_gate = (const float*)d_in[7];
    const float* shared_w_up   = (const float*)d_in[8];
    const float* shared_w_down = (const float*)d_in[9];
    float* out = (float*)d_out;

    cudaFuncSetAttribute(hmma2_kernel<256>, cudaFuncAttributeMaxDynamicSharedMemorySize, SMEM_H256);
    cudaFuncSetAttribute(hmma3_kernel<128>, cudaFuncAttributeMaxDynamicSharedMemorySize, SMEM_128);

    void *pxh, *pxl, *pwg, *pwu, *pwd, *psgw, *psuw, *psdw;
    void *pzh, *pzl, *phh, *phl;
    void *pg, *pu, *psg, *psu, *plog;
    void *bxh, *bxl, *bwrh, *bwrl;
    cudaGetSymbolAddress(&pxh, h_xh);   cudaGetSymbolAddress(&pxl, h_xl);
    cudaGetSymbolAddress(&pwg, h_wg);   cudaGetSymbolAddress(&pwu, h_wu);
    cudaGetSymbolAddress(&pwd, h_wd);
    cudaGetSymbolAddress(&psgw, h_sg);  cudaGetSymbolAddress(&psuw, h_su);
    cudaGetSymbolAddress(&psdw, h_sd);
    cudaGetSymbolAddress(&pzh, h_zh);   cudaGetSymbolAddress(&pzl, h_zl);
    cudaGetSymbolAddress(&phh, h_hh);   cudaGetSymbolAddress(&phl, h_hl);
    cudaGetSymbolAddress(&pg, g_gate);  cudaGetSymbolAddress(&pu, g_up);
    cudaGetSymbolAddress(&psg, g_sg);   cudaGetSymbolAddress(&psu, g_su);
    cudaGetSymbolAddress(&plog, g_logits);
    cudaGetSymbolAddress(&bxh, g_xh);   cudaGetSymbolAddress(&bxl, g_xl);
    cudaGetSymbolAddress(&bwrh, g_wrh); cudaGetSymbolAddress(&bwrl, g_wrl);

    // 1. conversions: x -> fp16 limbs; weights -> single fp16
    splitH_kernel<<<(T_TOK * HD / 4) / 256, 256>>>((const float4*)x, (__half*)pxh, (__half*)pxl, T_TOK * HD / 4);
    conv1_kernel<<<(HD * KI / 4) / 256, 256>>>((const float4*)w_gate, (__half*)pwg, HD * KI / 4);
    conv1_kernel<<<(HD * KI / 4) / 256, 256>>>((const float4*)w_up,   (__half*)pwu, HD * KI / 4);
    conv1_kernel<<<(ID * HD / 4) / 256, 256>>>((const float4*)w_down, (__half*)pwd, ID * HD / 4);
    conv1_kernel<<<(HD * I2 / 4) / 256, 256>>>((const float4*)shared_w_gate, (__half*)psgw, HD * I2 / 4);
    conv1_kernel<<<(HD * I2 / 4) / 256, 256>>>((const float4*)shared_w_up,   (__half*)psuw, HD * I2 / 4);
    conv1_kernel<<<(I2 * HD / 4) / 256, 256>>>((const float4*)shared_w_down, (__half*)psdw, I2 * HD / 4);

    // 2. router path in bf16x3 (precision-sensitive: top-k selection)
    split_kernel<<<(T_TOK * HD / 4) / 256, 256>>>((const float4*)x, (__nv_bfloat16*)bxh, (__nv_bfloat16*)bxl, T_TOK * HD / 4);
    split_kernel<<<(HD * NE / 4) / 256, 256>>>((const float4*)w_router, (__nv_bfloat16*)bwrh, (__nv_bfloat16*)bwrl, HD * NE / 4);
    mix_kernel<<<1, 128>>>(amplitudes);
    hmma3_kernel<128><<<dim3(T_TOK / BM, 1), 512, SMEM_128>>>(
        (const __nv_bfloat16*)bxh, (const __nv_bfloat16*)bxl,
        (const __nv_bfloat16*)bwrh, (const __nv_bfloat16*)bwrl, (float*)plog, NE, HD, 0);
    topk_kernel<<<T_TOK / 8, 256>>>(expert_scale);

    // 3. gate / up projections (fp16 2-pass)
    gemm2(pxh, pxl, pwg, (float*)pg, T_TOK, KI, HD, 0);
    gemm2(pxh, pxl, pwu, (float*)pu, T_TOK, KI, HD, 0);

    // 4. z = sum_k wk * silu(gate) * up -> fp16 limbs
    moe_mix_kernel<<<dim3(ID / 256, T_TOK), 256>>>();

    // 5. down projection: out = z @ w_down
    gemm2(pzh, pzl, pwd, out, T_TOK, HD, ID, 0);

    // 6. shared expert
    gemm2(pxh, pxl, psgw, (float*)psg, T_TOK, I2, HD, 0);
    gemm2(pxh, pxl, psuw, (float*)psu, T_TOK, I2, HD, 0);
    silu_mul_kernel<<<(T_TOK * I2) / 256, 256>>>();

    // 7. out += h @ shared_w_down
    gemm2(phh, phl, psdw, out, T_TOK, HD, I2, 1);
}

// round 9
// speedup vs baseline: 5.5712x; 1.4698x over previous
#include <cuda_runtime.h>
#include <cuda_bf16.h>
#include <cuda_fp16.h>
#include <math.h>
#include <float.h>
#include <stdint.h>

// ---------------- problem constants ----------------
#define T_TOK 8192
#define HD    2048
#define ID    1024
#define KQ    8
#define NE    128
#define KI    8192
#define I2    2048

// ---------------- fp32 scratch ----------------
__device__ float g_gate[67108864];   // [T, KI]
__device__ float g_up[67108864];     // [T, KI]
__device__ float g_sg[16777216];     // [T, I2]
__device__ float g_su[16777216];     // [T, I2]
__device__ float g_logits[1048576];  // [T, NE]
__device__ float g_wk[65536];        // [T, KQ]
__device__ float g_mix[1024];        // [NE, KQ]

// ---------------- fp16 operand scratch ----------------
__device__ __half h_x[16777216];                    // x [T,HD] single fp16
__device__ __half h_wg[16777216];                   // w_gate [HD,KI]
__device__ __half h_wu[16777216];                   // w_up
__device__ __half h_wd[2097152];                    // w_down [ID,HD]
__device__ __half h_sg[4194304];                    // shared_w_gate [HD,I2]
__device__ __half h_su[4194304];                    // shared_w_up
__device__ __half h_sd[4194304];                    // shared_w_down [I2,HD]
__device__ __half h_zh[8388608],  h_zl[8388608];    // z limbs [T,ID]
__device__ __half h_hh[16777216], h_hl[16777216];   // h limbs [T,I2]

// bf16 (router only)
__device__ __nv_bfloat16 g_xh[16777216], g_xl[16777216];
__device__ __nv_bfloat16 g_wrh[262144],  g_wrl[262144];

// ================= low-level helpers =================
__device__ __forceinline__ uint32_t smem_u32(const void* p) {
    uint32_t a;
    asm("{ .reg .u64 t; cvta.to.shared.u64 t, %1; cvt.u32.u64 %0, t; }" : "=r"(a) : "l"(p));
    return a;
}
__device__ __forceinline__ void cp16(uint32_t dst, const void* src) {
    asm volatile("cp.async.cg.shared.global [%0], [%1], 16;" :: "r"(dst), "l"(src));
}
__device__ __forceinline__ void cp_commit() {
    asm volatile("cp.async.commit_group;" ::: "memory");
}
template<int N> __device__ __forceinline__ void cp_wait() {
    asm volatile("cp.async.wait_group %0;" :: "n"(N) : "memory");
}
__device__ __forceinline__ void ldsm4(uint32_t* r, uint32_t addr) {
    asm volatile("ldmatrix.sync.aligned.m8n8.x4.shared.b16 {%0,%1,%2,%3}, [%4];"
                 : "=r"(r[0]), "=r"(r[1]), "=r"(r[2]), "=r"(r[3]) : "r"(addr));
}
__device__ __forceinline__ void ldsm4t(uint32_t* r, uint32_t addr) {
    asm volatile("ldmatrix.sync.aligned.m8n8.x4.trans.shared.b16 {%0,%1,%2,%3}, [%4];"
                 : "=r"(r[0]), "=r"(r[1]), "=r"(r[2]), "=r"(r[3]) : "r"(addr));
}
__device__ __forceinline__ void mma_bf16(float* d, const uint32_t* a, uint32_t b0, uint32_t b1) {
    asm volatile("mma.sync.aligned.m16n8k16.row.col.f32.bf16.bf16.f32 "
                 "{%0,%1,%2,%3}, {%4,%5,%6,%7}, {%8,%9}, {%0,%1,%2,%3};"
                 : "+f"(d[0]), "+f"(d[1]), "+f"(d[2]), "+f"(d[3])
                 : "r"(a[0]), "r"(a[1]), "r"(a[2]), "r"(a[3]), "r"(b0), "r"(b1));
}
__device__ __forceinline__ void mma_f16(float* d, const uint32_t* a, uint32_t b0, uint32_t b1) {
    asm volatile("mma.sync.aligned.m16n8k16.row.col.f32.f16.f16.f32 "
                 "{%0,%1,%2,%3}, {%4,%5,%6,%7}, {%8,%9}, {%0,%1,%2,%3};"
                 : "+f"(d[0]), "+f"(d[1]), "+f"(d[2]), "+f"(d[3])
                 : "r"(a[0]), "r"(a[1]), "r"(a[2]), "r"(a[3]), "r"(b0), "r"(b1));
}

#define BM 128
#define BK 64
#define A_STR 144
#define SA_HALF (BM * A_STR)

// ================= fp16 single-pass GEMM: C = A @ B =================
// A [M,Kd] fp16 row-major; B [Kd,N] fp16 row-major; C fp32.
// Block 128 x BN_T, BK=64, 512 threads (16 warps, warp 32 x BN_T/4), 2-stage.
template<int BN_T>
__global__ __launch_bounds__(512, 1)
void hmma1_kernel(const __half* __restrict__ A, const __half* __restrict__ B,
                  float* __restrict__ C, int N, int Kd, int acc)
{
    constexpr int WN      = BN_T / 4;
    constexpr int NH      = BN_T / 64;
    constexpr int B_STR_T = BN_T * 2 + 16;
    constexpr int SB      = BK * B_STR_T;
    constexpr int STAGEB  = SA_HALF + SB;
    constexpr int NBCH    = BN_T / 8;
    constexpr int B_ITERS = (BK * NBCH) / 512;

    extern __shared__ char smem[];
    const uint32_t sb = smem_u32(smem);
    const int tid  = threadIdx.x;
    const int lane = tid & 31;
    const int wid  = tid >> 5;
    const int wr   = wid & 3;
    const int wc   = wid >> 2;
    const int row0 = blockIdx.x * BM;
    const int col0 = blockIdx.y * BN_T;
    const int nch  = Kd >> 6;

    float accf[2][2 * NH][4];
#pragma unroll
    for (int i = 0; i < 2; i++)
#pragma unroll
        for (int j = 0; j < 2 * NH; j++)
#pragma unroll
            for (int q = 0; q < 4; q++) accf[i][j][q] = 0.f;

    auto load_stage = [&](int stg, int k0) {
        uint32_t s0 = sb + stg * STAGEB;
#pragma unroll
        for (int it = 0; it < 2; it++) {           // A: 128 rows x 8 chunks
            int idx = it * 512 + tid;
            int r = idx >> 3, c = idx & 7;
            cp16(s0 + r * A_STR + c * 16, A + (size_t)(row0 + r) * Kd + k0 + c * 8);
        }
#pragma unroll
        for (int it = 0; it < B_ITERS; it++) {     // B: 64 rows x NBCH chunks
            int idx = it * 512 + tid;
            int r = idx / NBCH, c = idx % NBCH;
            cp16(s0 + SA_HALF + r * B_STR_T + c * 16, B + (size_t)(k0 + r) * N + col0 + c * 8);
        }
        cp_commit();
    };

    load_stage(0, 0);

    const int a_row  = wr * 32 + (lane & 15);
    const int a_colb = (lane >> 4) << 4;
    const int b_row  = lane & 15;
    const int b_colb = (wc * WN + ((lane >> 4) << 3)) * 2;

    for (int ch = 0; ch < nch; ch++) {
        cp_wait<0>();
        __syncthreads();
        if (ch + 1 < nch) load_stage((ch + 1) & 1, (ch + 1) << 6);

        uint32_t sA = sb + (ch & 1) * STAGEB;
        uint32_t sB = sA + SA_HALF;

#pragma unroll
        for (int ks = 0; ks < 4; ks++) {
            const int k16 = ks << 4;
            uint32_t Af[2][4];
#pragma unroll
            for (int mi = 0; mi < 2; mi++)
                ldsm4(Af[mi], sA + (a_row + mi * 16) * A_STR + k16 * 2 + a_colb);
#pragma unroll
            for (int nh = 0; nh < NH; nh++) {
                uint32_t Bf[4];
                ldsm4t(Bf, sB + (b_row + k16) * B_STR_T + b_colb + nh * 32);
#pragma unroll
                for (int mi = 0; mi < 2; mi++)
#pragma unroll
                    for (int q = 0; q < 2; q++)
                        mma_f16(accf[mi][nh * 2 + q], Af[mi], Bf[q * 2], Bf[q * 2 + 1]);
            }
        }
    }

    const int er = row0 + wr * 32 + (lane >> 2);
    const int ec = col0 + wc * WN + (lane & 3) * 2;
#pragma unroll
    for (int mi = 0; mi < 2; mi++)
#pragma unroll
        for (int ni = 0; ni < 2 * NH; ni++) {
            float* p0 = C + (size_t)(er + mi * 16) * N + ec + ni * 8;
            float* p1 = p0 + 8 * N;
            float v0 = accf[mi][ni][0], v1 = accf[mi][ni][1];
            float v2 = accf[mi][ni][2], v3 = accf[mi][ni][3];
            if (acc) {
                float2 o0 = *(float2*)p0, o1 = *(float2*)p1;
                v0 += o0.x; v1 += o0.y; v2 += o1.x; v3 += o1.y;
            }
            *(float2*)p0 = make_float2(v0, v1);
            *(float2*)p1 = make_float2(v2, v3);
        }
}
#define SMEM_S256 (2 * (SA_HALF + BK * (256 * 2 + 16)))   // 104448

// ================= fp16 2-pass GEMM: C = (Ah+Al) @ B (down projections) =================
template<int BN_T>
__global__ __launch_bounds__(512, 1)
void hmma2_kernel(const __half* __restrict__ Ah, const __half* __restrict__ Al,
                  const __half* __restrict__ B, float* __restrict__ C,
                  int N, int Kd, int acc)
{
    constexpr int WN      = BN_T / 4;
    constexpr int NH      = BN_T / 64;
    constexpr int B_STR_T = BN_T * 2 + 16;
    constexpr int SB      = BK * B_STR_T;
    constexpr int STAGEB  = 2 * SA_HALF + SB;
    constexpr int NBCH    = BN_T / 8;
    constexpr int B_ITERS = (BK * NBCH) / 512;

    extern __shared__ char smem[];
    const uint32_t sb = smem_u32(smem);
    const int tid  = threadIdx.x;
    const int lane = tid & 31;
    const int wid  = tid >> 5;
    const int wr   = wid & 3;
    const int wc   = wid >> 2;
    const int row0 = blockIdx.x * BM;
    const int col0 = blockIdx.y * BN_T;
    const int nch  = Kd >> 6;

    float accf[2][2 * NH][4];
#pragma unroll
    for (int i = 0; i < 2; i++)
#pragma unroll
        for (int j = 0; j < 2 * NH; j++)
#pragma unroll
            for (int q = 0; q < 4; q++) accf[i][j][q] = 0.f;

    auto load_stage = [&](int stg, int k0) {
        uint32_t s0 = sb + stg * STAGEB;
#pragma unroll
        for (int it = 0; it < 2; it++) {
            int idx = it * 512 + tid;
            int r = idx >> 3, c = idx & 7;
            const __half* gh = Ah + (size_t)(row0 + r) * Kd + k0 + c * 8;
            const __half* gl = Al + (size_t)(row0 + r) * Kd + k0 + c * 8;
            uint32_t d = s0 + r * A_STR + c * 16;
            cp16(d, gh);
            cp16(d + SA_HALF, gl);
        }
#pragma unroll
        for (int it = 0; it < B_ITERS; it++) {
            int idx = it * 512 + tid;
            int r = idx / NBCH, c = idx % NBCH;
            cp16(s0 + 2 * SA_HALF + r * B_STR_T + c * 16, B + (size_t)(k0 + r) * N + col0 + c * 8);
        }
        cp_commit();
    };

    load_stage(0, 0);

    const int a_row  = wr * 32 + (lane & 15);
    const int a_colb = (lane >> 4) << 4;
    const int b_row  = lane & 15;
    const int b_colb = (wc * WN + ((lane >> 4) << 3)) * 2;

    for (int ch = 0; ch < nch; ch++) {
        cp_wait<0>();
        __syncthreads();
        if (ch + 1 < nch) load_stage((ch + 1) & 1, (ch + 1) << 6);

        uint32_t sA = sb + (ch & 1) * STAGEB;
        uint32_t sB = sA + 2 * SA_HALF;

#pragma unroll
        for (int ks = 0; ks < 4; ks++) {
            const int k16 = ks << 4;
            uint32_t Ahf[2][4], Alf[2][4];
#pragma unroll
            for (int mi = 0; mi < 2; mi++) {
                uint32_t ad = sA + (a_row + mi * 16) * A_STR + k16 * 2 + a_colb;
                ldsm4(Ahf[mi], ad);
                ldsm4(Alf[mi], ad + SA_HALF);
            }
#pragma unroll
            for (int nh = 0; nh < NH; nh++) {
                uint32_t Bf[4];
                ldsm4t(Bf, sB + (b_row + k16) * B_STR_T + b_colb + nh * 32);
#pragma unroll
                for (int mi = 0; mi < 2; mi++)
#pragma unroll
                    for (int q = 0; q < 2; q++) {
                        float* d = accf[mi][nh * 2 + q];
                        mma_f16(d, Ahf[mi], Bf[q * 2], Bf[q * 2 + 1]);
                        mma_f16(d, Alf[mi], Bf[q * 2], Bf[q * 2 + 1]);
                    }
            }
        }
    }

    const int er = row0 + wr * 32 + (lane >> 2);
    const int ec = col0 + wc * WN + (lane & 3) * 2;
#pragma unroll
    for (int mi = 0; mi < 2; mi++)
#pragma unroll
        for (int ni = 0; ni < 2 * NH; ni++) {
            float* p0 = C + (size_t)(er + mi * 16) * N + ec + ni * 8;
            float* p1 = p0 + 8 * N;
            float v0 = accf[mi][ni][0], v1 = accf[mi][ni][1];
            float v2 = accf[mi][ni][2], v3 = accf[mi][ni][3];
            if (acc) {
                float2 o0 = *(float2*)p0, o1 = *(float2*)p1;
                v0 += o0.x; v1 += o0.y; v2 += o1.x; v3 += o1.y;
            }
            *(float2*)p0 = make_float2(v0, v1);
            *(float2*)p1 = make_float2(v2, v3);
        }
}
#define SMEM_H256 (2 * (2 * SA_HALF + BK * (256 * 2 + 16)))   // 141312

// ================= bf16 hi/lo 3-pass GEMM (router only) =================
template<int BN_T>
__global__ __launch_bounds__(512, 1)
void hmma3_kernel(const __nv_bfloat16* __restrict__ Ah, const __nv_bfloat16* __restrict__ Al,
                  const __nv_bfloat16* __restrict__ Bh, const __nv_bfloat16* __restrict__ Bl,
                  float* __restrict__ C, int N, int Kd, int acc)
{
    constexpr int WN      = BN_T / 4;
    constexpr int NH      = BN_T / 64;
    constexpr int B_STR_T = BN_T * 2 + 16;
    constexpr int SB_HALF = BK * B_STR_T;
    constexpr int STAGEB  = 2 * SA_HALF + 2 * SB_HALF;
    constexpr int NBCH    = BN_T / 8;
    constexpr int B_ITERS = (BK * NBCH) / 512;

    extern __shared__ char smem[];
    const uint32_t sb = smem_u32(smem);
    const int tid  = threadIdx.x;
    const int lane = tid & 31;
    const int wid  = tid >> 5;
    const int wr   = wid & 3;
    const int wc   = wid >> 2;
    const int row0 = blockIdx.x * BM;
    const int col0 = blockIdx.y * BN_T;
    const int nch  = Kd >> 6;

    float accf[2][2 * NH][4];
#pragma unroll
    for (int i = 0; i < 2; i++)
#pragma unroll
        for (int j = 0; j < 2 * NH; j++)
#pragma unroll
            for (int q = 0; q < 4; q++) accf[i][j][q] = 0.f;

    auto load_stage = [&](int stg, int k0) {
        uint32_t s0 = sb + stg * STAGEB;
#pragma unroll
        for (int it = 0; it < 2; it++) {
            int idx = it * 512 + tid;
            int r = idx >> 3, c = idx & 7;
            const __nv_bfloat16* gh = Ah + (size_t)(row0 + r) * Kd + k0 + c * 8;
            const __nv_bfloat16* gl = Al + (size_t)(row0 + r) * Kd + k0 + c * 8;
            uint32_t d = s0 + r * A_STR + c * 16;
            cp16(d, gh);
            cp16(d + SA_HALF, gl);
        }
#pragma unroll
        for (int it = 0; it < B_ITERS; it++) {
            int idx = it * 512 + tid;
            int r = idx / NBCH, c = idx % NBCH;
            const __nv_bfloat16* gh = Bh + (size_t)(k0 + r) * N + col0 + c * 8;
            const __nv_bfloat16* gl = Bl + (size_t)(k0 + r) * N + col0 + c * 8;
            uint32_t d = s0 + 2 * SA_HALF + r * B_STR_T + c * 16;
            cp16(d, gh);
            cp16(d + SB_HALF, gl);
        }
        cp_commit();
    };

    load_stage(0, 0);

    const int a_row  = wr * 32 + (lane & 15);
    const int a_colb = (lane >> 4) << 4;
    const int b_row  = lane & 15;
    const int b_colb = (wc * WN + ((lane >> 4) << 3)) * 2;

    for (int ch = 0; ch < nch; ch++) {
        cp_wait<0>();
        __syncthreads();
        if (ch + 1 < nch) load_stage((ch + 1) & 1, (ch + 1) << 6);

        uint32_t sA = sb + (ch & 1) * STAGEB;
        uint32_t sB = sA + 2 * SA_HALF;

#pragma unroll
        for (int ks = 0; ks < 4; ks++) {
            const int k16 = ks << 4;
            uint32_t Ahf[2][4], Alf[2][4];
#pragma unroll
            for (int mi = 0; mi < 2; mi++) {
                uint32_t ad = sA + (a_row + mi * 16) * A_STR + k16 * 2 + a_colb;
                ldsm4(Ahf[mi], ad);
                ldsm4(Alf[mi], ad + SA_HALF);
            }
#pragma unroll
            for (int nh = 0; nh < NH; nh++) {
                uint32_t Bhf[4], Blf[4];
                uint32_t bd = sB + (b_row + k16) * B_STR_T + b_colb + nh * 32;
                ldsm4t(Bhf, bd);
                ldsm4t(Blf, bd + SB_HALF);
#pragma unroll
                for (int mi = 0; mi < 2; mi++)
#pragma unroll
                    for (int q = 0; q < 2; q++) {
                        float* d = accf[mi][nh * 2 + q];
                        mma_bf16(d, Ahf[mi], Bhf[q * 2], Bhf[q * 2 + 1]);
                        mma_bf16(d, Alf[mi], Bhf[q * 2], Bhf[q * 2 + 1]);
                        mma_bf16(d, Ahf[mi], Blf[q * 2], Blf[q * 2 + 1]);
                    }
            }
        }
    }

    const int er = row0 + wr * 32 + (lane >> 2);
    const int ec = col0 + wc * WN + (lane & 3) * 2;
#pragma unroll
    for (int mi = 0; mi < 2; mi++)
#pragma unroll
        for (int ni = 0; ni < 2 * NH; ni++) {
            float* p0 = C + (size_t)(er + mi * 16) * N + ec + ni * 8;
            float* p1 = p0 + 8 * N;
            float v0 = accf[mi][ni][0], v1 = accf[mi][ni][1];
            float v2 = accf[mi][ni][2], v3 = accf[mi][ni][3];
            if (acc) {
                float2 o0 = *(float2*)p0, o1 = *(float2*)p1;
                v0 += o0.x; v1 += o0.y; v2 += o1.x; v3 += o1.y;
            }
            *(float2*)p0 = make_float2(v0, v1);
            *(float2*)p1 = make_float2(v2, v3);
        }
}
#define SMEM_128 (2 * (2 * SA_HALF + 2 * (BK * (128 * 2 + 16))))

// ================= conversions =================
__global__ void conv1_kernel(const float4* __restrict__ src, __half* __restrict__ dst, int n4)
{
    int i = blockIdx.x * 256 + threadIdx.x;
    if (i >= n4) return;
    float4 v = src[i];
    __half2* dp = (__half2*)(dst + i * 4);
    dp[0] = __floats2half2_rn(v.x, v.y);
    dp[1] = __floats2half2_rn(v.z, v.w);
}

__global__ void split_kernel(const float4* __restrict__ src,
                             __nv_bfloat16* __restrict__ hi,
                             __nv_bfloat16* __restrict__ lo, int n4)
{
    int i = blockIdx.x * 256 + threadIdx.x;
    if (i >= n4) return;
    float4 v = src[i];
    __nv_bfloat16 h0 = __float2bfloat16_rn(v.x), h1 = __float2bfloat16_rn(v.y);
    __nv_bfloat16 h2 = __float2bfloat16_rn(v.z), h3 = __float2bfloat16_rn(v.w);
    __nv_bfloat162 hh0 = {h0, h1}, hh1 = {h2, h3};
    __nv_bfloat162 ll0 = {__float2bfloat16_rn(v.x - __bfloat162float(h0)),
                          __float2bfloat16_rn(v.y - __bfloat162float(h1))};
    __nv_bfloat162 ll1 = {__float2bfloat16_rn(v.z - __bfloat162float(h2)),
                          __float2bfloat16_rn(v.w - __bfloat162float(h3))};
    *(__nv_bfloat162*)(hi + i * 4)     = hh0;
    *(__nv_bfloat162*)(hi + i * 4 + 2) = hh1;
    *(__nv_bfloat162*)(lo + i * 4)     = ll0;
    *(__nv_bfloat162*)(lo + i * 4 + 2) = ll1;
}

// ================= amplitudes -> normalized mix =================
__global__ void mix_kernel(const float* __restrict__ amp)
{
    int e = threadIdx.x;
    if (e >= NE) return;
    float p[KQ];
    float s = 0.f;
#pragma unroll
    for (int k = 0; k < KQ; k++) {
        float a0 = amp[(e * KQ + k) * 2 + 0];
        float a1 = amp[(e * KQ + k) * 2 + 1];
        p[k] = a0 * a0 + a1 * a1;
        s += p[k];
    }
    float inv = 1.f / (s + 1e-8f);
#pragma unroll
    for (int k = 0; k < KQ; k++) g_mix[e * KQ + k] = p[k] * inv;
}

// ================= softmax + top-4 + collapse =================
__global__ void topk_kernel(const float* __restrict__ expert_scale)
{
    int lane = threadIdx.x & 31;
    int warp = threadIdx.x >> 5;
    int t = blockIdx.x * 8 + warp;
    const float* lrow = g_logits + (size_t)t * NE;

    float v[4];
#pragma unroll
    for (int j = 0; j < 4; j++) v[j] = lrow[lane + 32 * j];

    float m = fmaxf(fmaxf(v[0], v[1]), fmaxf(v[2], v[3]));
#pragma unroll
    for (int o = 16; o; o >>= 1) m = fmaxf(m, __shfl_xor_sync(0xffffffffu, m, o));

    float D = 0.f;
#pragma unroll
    for (int j = 0; j < 4; j++) D += expf(v[j] - m);
#pragma unroll
    for (int o = 16; o; o >>= 1) D += __shfl_xor_sync(0xffffffffu, D, o);

    float lv[4] = {v[0], v[1], v[2], v[3]};
    float selv[4];
    int   seli[4];
#pragma unroll
    for (int it = 0; it < 4; it++) {
        float bv = -FLT_MAX;
        int   bi = NE;
#pragma unroll
        for (int j = 0; j < 4; j++) {
            int e = lane + 32 * j;
            if (lv[j] > bv) { bv = lv[j]; bi = e; }
        }
#pragma unroll
        for (int o = 16; o; o >>= 1) {
            float ov = __shfl_xor_sync(0xffffffffu, bv, o);
            int   oi = __shfl_xor_sync(0xffffffffu, bi, o);
            if (ov > bv || (ov == bv && oi < bi)) { bv = ov; bi = oi; }
        }
        selv[it] = bv;
        seli[it] = bi;
        if ((bi & 31) == lane) lv[bi >> 5] = -FLT_MAX;
    }

    float ew[4];
    float S = 0.f;
#pragma unroll
    for (int it = 0; it < 4; it++) { ew[it] = expf(selv[it] - m); S += ew[it]; }
    float denom = S + 1e-8f * D;

    if (lane < KQ) {
        float acc = 0.f;
#pragma unroll
        for (int it = 0; it < 4; it++)
            acc += (ew[it] / denom) * expert_scale[seli[it]] * g_mix[seli[it] * KQ + lane];
        g_wk[t * KQ + lane] = acc;
    }
}

// ================= z = sum_k wk * silu(gate) * up  (writes fp16 limbs) =================
__global__ void moe_mix_kernel()
{
    int t = blockIdx.y;
    int i = blockIdx.x * 256 + threadIdx.x;
    __shared__ float w[KQ];
    if (threadIdx.x < KQ) w[threadIdx.x] = g_wk[t * KQ + threadIdx.x];
    __syncthreads();
    float acc = 0.f;
#pragma unroll
    for (int k = 0; k < KQ; k++) {
        size_t off = (size_t)t * KI + k * ID + i;
        float g = g_gate[off];
        float u = g_up[off];
        acc += w[k] * (g / (1.f + expf(-g))) * u;
    }
    size_t zo = (size_t)t * ID + i;
    __half h = __float2half_rn(acc);
    h_zh[zo] = h;
    h_zl[zo] = __float2half_rn(acc - __half2float(h));
}

// ================= shared expert elementwise (writes fp16 limbs) =================
__global__ void silu_mul_kernel()
{
    size_t idx = (size_t)blockIdx.x * 256 + threadIdx.x;
    float g = g_sg[idx];
    float u = g_su[idx];
    float v = (g / (1.f + expf(-g))) * u;
    __half h = __float2half_rn(v);
    h_hh[idx] = h;
    h_hl[idx] = __float2half_rn(v - __half2float(h));
}

// ================= host side =================
static void gemm1(const void* A, const void* B, float* C, int M, int N, int Kd, int acc)
{
    dim3 grid(M / BM, N / 256);
    hmma1_kernel<256><<<grid, 512, SMEM_S256>>>(
        (const __half*)A, (const __half*)B, C, N, Kd, acc);
}
static void gemm2(const void* Ah, const void* Al, const void* B,
                  float* C, int M, int N, int Kd, int acc)
{
    dim3 grid(M / BM, N / 256);
    hmma2_kernel<256><<<grid, 512, SMEM_H256>>>(
        (const __half*)Ah, (const __half*)Al, (const __half*)B, C, N, Kd, acc);
}

extern "C" void kernel_launch(void* const* d_in, const int* in_sizes, int n_in,
                              void* d_out, int out_size)
{
    const float* x             = (const float*)d_in[0];
    const float* w_router      = (const float*)d_in[1];
    const float* w_gate        = (const float*)d_in[2];
    const float* w_up          = (const float*)d_in[3];
    const float* w_down        = (const float*)d_in[4];
    const float* amplitudes    = (const float*)d_in[5];
    const float* expert_scale  = (const float*)d_in[6];
    const float* shared_w_gate = (const float*)d_in[7];
    const float* shared_w_up   = (const float*)d_in[8];
    const float* shared_w_down = (const float*)d_in[9];
    float* out = (float*)d_out;

    cudaFuncSetAttribute(hmma1_kernel<256>, cudaFuncAttributeMaxDynamicSharedMemorySize, SMEM_S256);
    cudaFuncSetAttribute(hmma2_kernel<256>, cudaFuncAttributeMaxDynamicSharedMemorySize, SMEM_H256);
    cudaFuncSetAttribute(hmma3_kernel<128>, cudaFuncAttributeMaxDynamicSharedMemorySize, SMEM_128);

    void *px, *pwg, *pwu, *pwd, *psgw, *psuw, *psdw;
    void *pzh, *pzl, *phh, *phl;
    void *pg, *pu, *psg, *psu, *plog;
    void *bxh, *bxl, *bwrh, *bwrl;
    cudaGetSymbolAddress(&px, h_x);
    cudaGetSymbolAddress(&pwg, h_wg);   cudaGetSymbolAddress(&pwu, h_wu);
    cudaGetSymbolAddress(&pwd, h_wd);
    cudaGetSymbolAddress(&psgw, h_sg);  cudaGetSymbolAddress(&psuw, h_su);
    cudaGetSymbolAddress(&psdw, h_sd);
    cudaGetSymbolAddress(&pzh, h_zh);   cudaGetSymbolAddress(&pzl, h_zl);
    cudaGetSymbolAddress(&phh, h_hh);   cudaGetSymbolAddress(&phl, h_hl);
    cudaGetSymbolAddress(&pg, g_gate);  cudaGetSymbolAddress(&pu, g_up);
    cudaGetSymbolAddress(&psg, g_sg);   cudaGetSymbolAddress(&psu, g_su);
    cudaGetSymbolAddress(&plog, g_logits);
    cudaGetSymbolAddress(&bxh, g_xh);   cudaGetSymbolAddress(&bxl, g_xl);
    cudaGetSymbolAddress(&bwrh, g_wrh); cudaGetSymbolAddress(&bwrl, g_wrl);

    // 1. conversions: x and weights -> single fp16
    conv1_kernel<<<(T_TOK * HD / 4) / 256, 256>>>((const float4*)x, (__half*)px, T_TOK * HD / 4);
    conv1_kernel<<<(HD * KI / 4) / 256, 256>>>((const float4*)w_gate, (__half*)pwg, HD * KI / 4);
    conv1_kernel<<<(HD * KI / 4) / 256, 256>>>((const float4*)w_up,   (__half*)pwu, HD * KI / 4);
    conv1_kernel<<<(ID * HD / 4) / 256, 256>>>((const float4*)w_down, (__half*)pwd, ID * HD / 4);
    conv1_kernel<<<(HD * I2 / 4) / 256, 256>>>((const float4*)shared_w_gate, (__half*)psgw, HD * I2 / 4);
    conv1_kernel<<<(HD * I2 / 4) / 256, 256>>>((const float4*)shared_w_up,   (__half*)psuw, HD * I2 / 4);
    conv1_kernel<<<(I2 * HD / 4) / 256, 256>>>((const float4*)shared_w_down, (__half*)psdw, I2 * HD / 4);

    // 2. router path in bf16x3 (precision-sensitive: top-k selection)
    split_kernel<<<(T_TOK * HD / 4) / 256, 256>>>((const float4*)x, (__nv_bfloat16*)bxh, (__nv_bfloat16*)bxl, T_TOK * HD / 4);
    split_kernel<<<(HD * NE / 4) / 256, 256>>>((const float4*)w_router, (__nv_bfloat16*)bwrh, (__nv_bfloat16*)bwrl, HD * NE / 4);
    mix_kernel<<<1, 128>>>(amplitudes);
    hmma3_kernel<128><<<dim3(T_TOK / BM, 1), 512, SMEM_128>>>(
        (const __nv_bfloat16*)bxh, (const __nv_bfloat16*)bxl,
        (const __nv_bfloat16*)bwrh, (const __nv_bfloat16*)bwrl, (float*)plog, NE, HD, 0);
    topk_kernel<<<T_TOK / 8, 256>>>(expert_scale);

    // 3. gate / up projections (fp16 single-pass)
    gemm1(px, pwg, (float*)pg, T_TOK, KI, HD, 0);
    gemm1(px, pwu, (float*)pu, T_TOK, KI, HD, 0);

    // 4. z = sum_k wk * silu(gate) * up -> fp16 limbs
    moe_mix_kernel<<<dim3(ID / 256, T_TOK), 256>>>();

    // 5. down projection: out = z @ w_down (2-pass A for accuracy hedge)
    gemm2(pzh, pzl, pwd, out, T_TOK, HD, ID, 0);

    // 6. shared expert (fp16 single-pass)
    gemm1(px, psgw, (float*)psg, T_TOK, I2, HD, 0);
    gemm1(px, psuw, (float*)psu, T_TOK, I2, HD, 0);
    silu_mul_kernel<<<(T_TOK * I2) / 256, 256>>>();

    // 7. out += h @ shared_w_down (2-pass A)
    gemm2(phh, phl, psdw, out, T_TOK, HD, I2, 1);
}